// round 16
// baseline (speedup 1.0000x reference)
#include <cuda_runtime.h>
#include <cuda_fp16.h>
#include <math.h>
#include <cstdint>

#define D_MODEL 1024
#define NH 16
#define HD 64
#define BATCH 2
#define SEQ 2048
#define MTOT (BATCH*SEQ)      // 4096
#define NQKV (3*D_MODEL)      // 3072

// ---------------------------------------------------------------------------
// Scratch (no cudaMalloc allowed)
// ---------------------------------------------------------------------------
static __device__ __align__(128) __half g_x[(size_t)MTOT * D_MODEL];
static __device__ __align__(128) __half g_wqkv[(size_t)D_MODEL * NQKV];
static __device__ __align__(128) __half g_qkv[(size_t)MTOT * NQKV];
static __device__ __align__(128) __half g_ctx[(size_t)MTOT * D_MODEL];
static __device__ __align__(128) __half g_wout[(size_t)D_MODEL * D_MODEL];

// ---------------------------------------------------------------------------
// merged fp32 -> fp16 cast of x, Wqkv, Wout in one launch
// ---------------------------------------------------------------------------
#define NX2  (MTOT * D_MODEL / 2)
#define NWQ2 (D_MODEL * NQKV / 2)
#define NWO2 (D_MODEL * D_MODEL / 2)
__global__ __launch_bounds__(256) void cast_all(
    const float2* __restrict__ x, const float2* __restrict__ wq,
    const float2* __restrict__ wo,
    __half2* __restrict__ xo, __half2* __restrict__ wqo,
    __half2* __restrict__ woo)
{
    int i = blockIdx.x * blockDim.x + threadIdx.x;
    const int total = NX2 + NWQ2 + NWO2;
    for (; i < total; i += gridDim.x * blockDim.x) {
        float2 v;
        __half2* dst;
        int j;
        if (i < NX2)            { v = x[i];              dst = xo;  j = i; }
        else if (i < NX2+NWQ2)  { j = i - NX2;  v = wq[j]; dst = wqo; }
        else                    { j = i - NX2 - NWQ2; v = wo[j]; dst = woo; }
        dst[j] = __halves2half2(__float2half_rn(v.x), __float2half_rn(v.y));
    }
}

// ---------------------------------------------------------------------------
// mma / ldmatrix / cp.async helpers
// ---------------------------------------------------------------------------
__device__ __forceinline__ void cpa16(void* s, const void* g) {
    uint32_t sa = (uint32_t)__cvta_generic_to_shared(s);
    asm volatile("cp.async.ca.shared.global [%0], [%1], 16;\n" :: "r"(sa), "l"(g));
}
__device__ __forceinline__ void cp_commit() {
    asm volatile("cp.async.commit_group;\n" ::: "memory");
}
__device__ __forceinline__ void cp_wait0() {
    asm volatile("cp.async.wait_group 0;\n" ::: "memory");
}
__device__ __forceinline__ void ldsm4(uint32_t& r0, uint32_t& r1, uint32_t& r2,
                                      uint32_t& r3, const void* p) {
    uint32_t a = (uint32_t)__cvta_generic_to_shared(p);
    asm volatile("ldmatrix.sync.aligned.m8n8.x4.shared.b16 {%0,%1,%2,%3}, [%4];"
                 : "=r"(r0), "=r"(r1), "=r"(r2), "=r"(r3) : "r"(a));
}
__device__ __forceinline__ void ldsm4t(uint32_t& r0, uint32_t& r1, uint32_t& r2,
                                       uint32_t& r3, const void* p) {
    uint32_t a = (uint32_t)__cvta_generic_to_shared(p);
    asm volatile("ldmatrix.sync.aligned.m8n8.x4.trans.shared.b16 {%0,%1,%2,%3}, [%4];"
                 : "=r"(r0), "=r"(r1), "=r"(r2), "=r"(r3) : "r"(a));
}
__device__ __forceinline__ void mma16816(float* d, const uint32_t* a,
                                         const uint32_t* b) {
    asm volatile(
        "mma.sync.aligned.m16n8k16.row.col.f32.f16.f16.f32 "
        "{%0,%1,%2,%3}, {%4,%5,%6,%7}, {%8,%9}, {%0,%1,%2,%3};"
        : "+f"(d[0]), "+f"(d[1]), "+f"(d[2]), "+f"(d[3])
        : "r"(a[0]), "r"(a[1]), "r"(a[2]), "r"(a[3]), "r"(b[0]), "r"(b[1]));
}
__device__ __forceinline__ uint32_t h2pack(__half a, __half b) {
    __half2 t = __halves2half2(a, b);
    return *reinterpret_cast<uint32_t*>(&t);
}
__device__ __forceinline__ uint32_t packf2(float a, float b) {
    __half2 t = __floats2half2_rn(a, b);
    return *reinterpret_cast<uint32_t*>(&t);
}
__device__ __forceinline__ uint32_t ex2h2(uint32_t x) {
    asm("ex2.approx.f16x2 %0, %0;" : "+r"(x));
    return x;
}

// ---------------------------------------------------------------------------
// fp16 tensor-core GEMM, single-barrier 2-stage pipeline (unchanged, R14):
// per stage: wait0 -> sync -> issue loads(st^1) -> compute(st).
// C[M,N] = A[M,K] @ B[K,N] + bias[N]; BK=64, 128x128 tile, 256 thr.
// ---------------------------------------------------------------------------
#define BM 128
#define BN 128
#define BK 64
#define SA2 72
#define SB2 136
#define GEMM_SMEM_BYTES (35840 * 2)

__global__ __launch_bounds__(256) void gemm_f16(
    const __half* __restrict__ A,
    const __half* __restrict__ B,
    const float* __restrict__ bias,
    float* __restrict__ Cf,
    __half* __restrict__ Ch,
    int M, int N, int K)
{
    extern __shared__ __align__(16) __half sm[];
    __half* AH[2] = { sm,          sm + 9216 };
    __half* BS[2] = { sm + 18432,  sm + 27136 };

    const int tid  = threadIdx.x;
    const int lane = tid & 31;
    const int wid  = tid >> 5;
    const int wm   = (wid & 1) * 64;
    const int wn   = (wid >> 1) * 32;
    const int bm   = blockIdx.y * BM;
    const int bn   = blockIdx.x * BN;

    float acc[4][4][4];
    #pragma unroll
    for (int i = 0; i < 4; i++)
        #pragma unroll
        for (int j = 0; j < 4; j++)
            #pragma unroll
            for (int r = 0; r < 4; r++) acc[i][j][r] = 0.f;

    const int NK = K / BK;

    #define G_LOAD(ST, KS) do {                                               \
        const int k0 = (KS) * BK;                                             \
        _Pragma("unroll")                                                     \
        for (int s = 0; s < 4; s++) {                                         \
            int t = tid + s * 256;                                            \
            int row = t >> 3, ch = (t & 7) * 8;                               \
            cpa16(AH[ST] + row * SA2 + ch,                                    \
                  A + (size_t)(bm + row) * K + k0 + ch);                      \
        }                                                                     \
        _Pragma("unroll")                                                     \
        for (int s = 0; s < 4; s++) {                                         \
            int t = tid + s * 256;                                            \
            int row = t >> 4, ch = (t & 15) * 8;                              \
            cpa16(BS[ST] + row * SB2 + ch,                                    \
                  B + (size_t)(k0 + row) * N + bn + ch);                      \
        }                                                                     \
        cp_commit();                                                          \
    } while (0)

    G_LOAD(0, 0);

    const int arow = lane & 15;
    const int acol = (lane >> 4) * 8;

    for (int ks = 0; ks < NK; ks++) {
        const int st = ks & 1;
        cp_wait0();
        __syncthreads();
        if (ks + 1 < NK) G_LOAD(st ^ 1, ks + 1);

        #pragma unroll
        for (int kk = 0; kk < 4; kk++) {
            uint32_t af[4][4];
            uint32_t bf[4][2];
            #pragma unroll
            for (int mf = 0; mf < 4; mf++)
                ldsm4(af[mf][0], af[mf][1], af[mf][2], af[mf][3],
                      &AH[st][(wm + mf * 16 + arow) * SA2 + kk * 16 + acol]);
            #pragma unroll
            for (int nf2 = 0; nf2 < 2; nf2++) {
                uint32_t r0, r1, r2, r3;
                ldsm4t(r0, r1, r2, r3,
                       &BS[st][(kk * 16 + arow) * SB2 + wn + nf2 * 16 + acol]);
                bf[nf2 * 2 + 0][0] = r0; bf[nf2 * 2 + 0][1] = r1;
                bf[nf2 * 2 + 1][0] = r2; bf[nf2 * 2 + 1][1] = r3;
            }
            #pragma unroll
            for (int mf = 0; mf < 4; mf++)
                #pragma unroll
                for (int nf = 0; nf < 4; nf++)
                    mma16816(acc[mf][nf], af[mf], bf[nf]);
        }
    }
    #undef G_LOAD

    const int r  = lane >> 2;
    const int c2 = (lane & 3) * 2;
    #pragma unroll
    for (int nf = 0; nf < 4; nf++) {
        const int col = bn + wn + nf * 8 + c2;
        const float b0 = bias[col];
        const float b1 = bias[col + 1];
        #pragma unroll
        for (int mf = 0; mf < 4; mf++) {
            const int row0 = bm + wm + mf * 16 + r;
            float v00 = acc[mf][nf][0] + b0, v01 = acc[mf][nf][1] + b1;
            float v10 = acc[mf][nf][2] + b0, v11 = acc[mf][nf][3] + b1;
            if (Cf) {
                *(float2*)(Cf + (size_t)row0 * N + col) = make_float2(v00, v01);
                *(float2*)(Cf + (size_t)(row0 + 8) * N + col) = make_float2(v10, v11);
            } else {
                *(uint32_t*)(Ch + (size_t)row0 * N + col) =
                    h2pack(__float2half_rn(v00), __float2half_rn(v01));
                *(uint32_t*)(Ch + (size_t)(row0 + 8) * N + col) =
                    h2pack(__float2half_rn(v10), __float2half_rn(v11));
            }
        }
    }
}

// ---------------------------------------------------------------------------
// Persistent tensor-core flash attention:
// S in log2 domain (scale folded into Q), P via packed ex2.approx.f16x2,
// row sums via ones-mma, one barrier per k-iteration.
// OCCUPANCY BUMP: 5 CTAs/SM (launch_bounds caps regs at 102), grid=740.
// smem 5 x 36864 = 184 KB <= 228 KB.
// ---------------------------------------------------------------------------
#define AST 72
#define ATILE (64 * AST)
#define NTILES (BATCH * NH * (SEQ / 64))   // 1024
#define ATTN_GRID 740                      // 148 SMs x 5 CTAs

__global__ __launch_bounds__(128, 5) void attn_f16(
    const __half* __restrict__ qkv,
    __half* __restrict__ ctx)
{
    extern __shared__ __half smA[];

    const int tid  = threadIdx.x;
    const int lane = tid & 31;
    const int wid  = tid >> 5;

    const int krow = lane & 15;
    const int kcb  = (lane >> 4) * 8;

    const __half2 qscale = __halves2half2(__float2half_rn(0.18033688f),
                                          __float2half_rn(0.18033688f));
    const uint32_t ones_b[2] = { 0x3C003C00u, 0x3C003C00u };

    for (int tile = blockIdx.x; tile < NTILES; tile += ATTN_GRID) {
        const int qt = tile & 31;
        const int h  = (tile >> 5) & 15;
        const int b  = tile >> 9;

        const __half* qb = qkv + (size_t)b * SEQ * NQKV + h * HD;

        #pragma unroll
        for (int i = 0; i < 4; i++) {
            int c = tid + i * 128;
            int r = c >> 3, cc = (c & 7) * 8;
            cpa16(&smA[r * AST + cc], qb + (size_t)(qt * 64 + r) * NQKV + cc);
        }
        cp_commit(); cp_wait0(); __syncthreads();

        uint32_t qf[4][4];
        {
            const int row = wid * 16 + (lane & 15);
            const int cb  = (lane >> 4) * 8;
            #pragma unroll
            for (int j = 0; j < 4; j++) {
                ldsm4(qf[j][0], qf[j][1], qf[j][2], qf[j][3],
                      &smA[row * AST + j * 16 + cb]);
                #pragma unroll
                for (int r = 0; r < 4; r++) {
                    __half2 v = *reinterpret_cast<__half2*>(&qf[j][r]);
                    v = __hmul2(v, qscale);
                    qf[j][r] = *reinterpret_cast<uint32_t*>(&v);
                }
            }
        }
        __syncthreads();

        float oacc[8][4];
        #pragma unroll
        for (int nf = 0; nf < 8; nf++)
            #pragma unroll
            for (int r = 0; r < 4; r++) oacc[nf][r] = 0.f;
        float osum[4] = {0.f, 0.f, 0.f, 0.f};

        #define PREFETCH(KT, ST) do {                                          \
            __half* bp = smA + (ST) * 2 * ATILE;                               \
            _Pragma("unroll")                                                  \
            for (int i = 0; i < 4; i++) {                                      \
                int c = tid + i * 128;                                         \
                int r = c >> 3, cc = (c & 7) * 8;                              \
                size_t go = (size_t)((KT) * 64 + r) * NQKV + cc;               \
                cpa16(bp + r * AST + cc,          qb + D_MODEL + go);          \
                cpa16(bp + ATILE + r * AST + cc,  qb + 2 * D_MODEL + go);      \
            }                                                                  \
            cp_commit();                                                       \
        } while (0)

        PREFETCH(0, 0);

        for (int kt = 0; kt < SEQ / 64; kt++) {
            const int st = kt & 1;
            cp_wait0();
            __syncthreads();
            if (kt + 1 < SEQ / 64) PREFETCH(kt + 1, st ^ 1);

            const __half* KT_ = smA + st * 2 * ATILE;
            const __half* VT_ = KT_ + ATILE;

            float sacc[8][4];
            #pragma unroll
            for (int nf = 0; nf < 8; nf++)
                #pragma unroll
                for (int r = 0; r < 4; r++) sacc[nf][r] = 0.f;

            #pragma unroll
            for (int j = 0; j < 4; j++) {
                uint32_t bh[8][2];
                #pragma unroll
                for (int n2 = 0; n2 < 4; n2++) {
                    uint32_t t0, t1, t2, t3;
                    ldsm4(t0, t1, t2, t3,
                          &KT_[(n2 * 16 + krow) * AST + j * 16 + kcb]);
                    bh[n2*2][0] = t0; bh[n2*2][1] = t2;
                    bh[n2*2+1][0] = t1; bh[n2*2+1][1] = t3;
                }
                #pragma unroll
                for (int nf = 0; nf < 8; nf++)
                    mma16816(sacc[nf], qf[j], bh[nf]);
            }

            uint32_t ph[4][4];
            #pragma unroll
            for (int j = 0; j < 4; j++) {
                #pragma unroll
                for (int half = 0; half < 2; half++) {
                    ph[j][half * 2 + 0] =
                        ex2h2(packf2(sacc[2*j + half][0], sacc[2*j + half][1]));
                    ph[j][half * 2 + 1] =
                        ex2h2(packf2(sacc[2*j + half][2], sacc[2*j + half][3]));
                }
            }

            #pragma unroll
            for (int j = 0; j < 4; j++)
                mma16816(osum, ph[j], ones_b);

            #pragma unroll
            for (int j = 0; j < 4; j++) {
                uint32_t vh[8][2];
                #pragma unroll
                for (int n2 = 0; n2 < 4; n2++) {
                    uint32_t t0, t1, t2, t3;
                    ldsm4t(t0, t1, t2, t3,
                           &VT_[(j * 16 + krow) * AST + n2 * 16 + kcb]);
                    vh[n2*2][0] = t0; vh[n2*2][1] = t1;
                    vh[n2*2+1][0] = t2; vh[n2*2+1][1] = t3;
                }
                #pragma unroll
                for (int nf = 0; nf < 8; nf++)
                    mma16816(oacc[nf], ph[j], vh[nf]);
            }
        }
        #undef PREFETCH

        const float inv0 = 1.f / osum[0];
        const float inv1 = 1.f / osum[2];
        const int r0 = lane >> 2;
        const int colb = h * HD + (lane & 3) * 2;
        const size_t row0 = (size_t)b * SEQ + qt * 64 + wid * 16 + r0;
        #pragma unroll
        for (int nf = 0; nf < 8; nf++) {
            const int col = colb + nf * 8;
            *(uint32_t*)(ctx + row0 * D_MODEL + col) =
                h2pack(__float2half_rn(oacc[nf][0] * inv0),
                       __float2half_rn(oacc[nf][1] * inv0));
            *(uint32_t*)(ctx + (row0 + 8) * D_MODEL + col) =
                h2pack(__float2half_rn(oacc[nf][2] * inv1),
                       __float2half_rn(oacc[nf][3] * inv1));
        }
        __syncthreads();
    }
}

// ---------------------------------------------------------------------------
extern "C" void kernel_launch(void* const* d_in, const int* in_sizes, int n_in,
                              void* d_out, int out_size)
{
    const float* x    = (const float*)d_in[0];
    const float* Wqkv = (const float*)d_in[1];
    const float* bqkv = (const float*)d_in[2];
    const float* Wout = (const float*)d_in[3];
    const float* bout = (const float*)d_in[4];
    float* out = (float*)d_out;

    __half *xc, *wq, *qv, *cx, *wo;
    cudaGetSymbolAddress((void**)&xc, g_x);
    cudaGetSymbolAddress((void**)&wq, g_wqkv);
    cudaGetSymbolAddress((void**)&qv, g_qkv);
    cudaGetSymbolAddress((void**)&cx, g_ctx);
    cudaGetSymbolAddress((void**)&wo, g_wout);

    cast_all<<<2048, 256>>>((const float2*)x, (const float2*)Wqkv,
                            (const float2*)Wout,
                            (__half2*)xc, (__half2*)wq, (__half2*)wo);

    cudaFuncSetAttribute(gemm_f16, cudaFuncAttributeMaxDynamicSharedMemorySize,
                         GEMM_SMEM_BYTES);

    // 1) QKV projection -> fp16 qkv
    dim3 g1(NQKV / BN, MTOT / BM);
    gemm_f16<<<g1, 256, GEMM_SMEM_BYTES>>>(
        xc, wq, bqkv, nullptr, qv, MTOT, NQKV, D_MODEL);

    // 2) Persistent attention -> fp16 ctx (5 CTAs/SM, all SMs)
    size_t smem = (size_t)2 * 2 * ATILE * sizeof(__half);  // 36864 B
    cudaFuncSetAttribute(attn_f16, cudaFuncAttributeMaxDynamicSharedMemorySize,
                         (int)smem);
    attn_f16<<<ATTN_GRID, 128, smem>>>(qv, cx);

    // 3) Output projection -> fp32 out
    dim3 g3(D_MODEL / BN, MTOT / BM);
    gemm_f16<<<g3, 256, GEMM_SMEM_BYTES>>>(
        cx, wo, bout, out, nullptr, MTOT, D_MODEL, D_MODEL);
}

// round 17
// speedup vs baseline: 1.5706x; 1.5706x over previous
#include <cuda_runtime.h>
#include <cuda_fp16.h>
#include <math.h>
#include <cstdint>

#define D_MODEL 1024
#define NH 16
#define HD 64
#define BATCH 2
#define SEQ 2048
#define MTOT (BATCH*SEQ)      // 4096
#define NQKV (3*D_MODEL)      // 3072

// ---------------------------------------------------------------------------
// Scratch (no cudaMalloc allowed)
// ---------------------------------------------------------------------------
static __device__ __align__(128) __half g_x[(size_t)MTOT * D_MODEL];
static __device__ __align__(128) __half g_wqkv[(size_t)D_MODEL * NQKV];
static __device__ __align__(128) __half g_qkv[(size_t)MTOT * NQKV];
static __device__ __align__(128) __half g_ctx[(size_t)MTOT * D_MODEL];
static __device__ __align__(128) __half g_wout[(size_t)D_MODEL * D_MODEL];

// ---------------------------------------------------------------------------
// merged fp32 -> fp16 cast of x, Wqkv, Wout in one launch
// ---------------------------------------------------------------------------
#define NX2  (MTOT * D_MODEL / 2)
#define NWQ2 (D_MODEL * NQKV / 2)
#define NWO2 (D_MODEL * D_MODEL / 2)
__global__ __launch_bounds__(256) void cast_all(
    const float2* __restrict__ x, const float2* __restrict__ wq,
    const float2* __restrict__ wo,
    __half2* __restrict__ xo, __half2* __restrict__ wqo,
    __half2* __restrict__ woo)
{
    int i = blockIdx.x * blockDim.x + threadIdx.x;
    const int total = NX2 + NWQ2 + NWO2;
    for (; i < total; i += gridDim.x * blockDim.x) {
        float2 v;
        __half2* dst;
        int j;
        if (i < NX2)            { v = x[i];              dst = xo;  j = i; }
        else if (i < NX2+NWQ2)  { j = i - NX2;  v = wq[j]; dst = wqo; }
        else                    { j = i - NX2 - NWQ2; v = wo[j]; dst = woo; }
        dst[j] = __halves2half2(__float2half_rn(v.x), __float2half_rn(v.y));
    }
}

// ---------------------------------------------------------------------------
// mma / ldmatrix / cp.async helpers
// ---------------------------------------------------------------------------
__device__ __forceinline__ void cpa16(void* s, const void* g) {
    uint32_t sa = (uint32_t)__cvta_generic_to_shared(s);
    asm volatile("cp.async.ca.shared.global [%0], [%1], 16;\n" :: "r"(sa), "l"(g));
}
__device__ __forceinline__ void cp_commit() {
    asm volatile("cp.async.commit_group;\n" ::: "memory");
}
__device__ __forceinline__ void cp_wait0() {
    asm volatile("cp.async.wait_group 0;\n" ::: "memory");
}
__device__ __forceinline__ void ldsm4(uint32_t& r0, uint32_t& r1, uint32_t& r2,
                                      uint32_t& r3, const void* p) {
    uint32_t a = (uint32_t)__cvta_generic_to_shared(p);
    asm volatile("ldmatrix.sync.aligned.m8n8.x4.shared.b16 {%0,%1,%2,%3}, [%4];"
                 : "=r"(r0), "=r"(r1), "=r"(r2), "=r"(r3) : "r"(a));
}
__device__ __forceinline__ void ldsm4t(uint32_t& r0, uint32_t& r1, uint32_t& r2,
                                       uint32_t& r3, const void* p) {
    uint32_t a = (uint32_t)__cvta_generic_to_shared(p);
    asm volatile("ldmatrix.sync.aligned.m8n8.x4.trans.shared.b16 {%0,%1,%2,%3}, [%4];"
                 : "=r"(r0), "=r"(r1), "=r"(r2), "=r"(r3) : "r"(a));
}
__device__ __forceinline__ void mma16816(float* d, const uint32_t* a,
                                         const uint32_t* b) {
    asm volatile(
        "mma.sync.aligned.m16n8k16.row.col.f32.f16.f16.f32 "
        "{%0,%1,%2,%3}, {%4,%5,%6,%7}, {%8,%9}, {%0,%1,%2,%3};"
        : "+f"(d[0]), "+f"(d[1]), "+f"(d[2]), "+f"(d[3])
        : "r"(a[0]), "r"(a[1]), "r"(a[2]), "r"(a[3]), "r"(b[0]), "r"(b[1]));
}
__device__ __forceinline__ uint32_t h2pack(__half a, __half b) {
    __half2 t = __halves2half2(a, b);
    return *reinterpret_cast<uint32_t*>(&t);
}
__device__ __forceinline__ uint32_t packf2(float a, float b) {
    __half2 t = __floats2half2_rn(a, b);
    return *reinterpret_cast<uint32_t*>(&t);
}
__device__ __forceinline__ uint32_t ex2h2(uint32_t x) {
    asm("ex2.approx.f16x2 %0, %0;" : "+r"(x));
    return x;
}

// ---------------------------------------------------------------------------
// fp16 tensor-core GEMM, single-barrier 2-stage pipeline:
// per stage: wait0 -> sync -> issue loads(st^1) -> compute(st).
// C[M,N] = A[M,K] @ B[K,N] + bias[N]; BK=64, 128x128 tile, 256 thr.
// ---------------------------------------------------------------------------
#define BM 128
#define BN 128
#define BK 64
#define SA2 72
#define SB2 136
#define GEMM_SMEM_BYTES (35840 * 2)

__global__ __launch_bounds__(256) void gemm_f16(
    const __half* __restrict__ A,
    const __half* __restrict__ B,
    const float* __restrict__ bias,
    float* __restrict__ Cf,
    __half* __restrict__ Ch,
    int M, int N, int K)
{
    extern __shared__ __align__(16) __half sm[];
    __half* AH[2] = { sm,          sm + 9216 };
    __half* BS[2] = { sm + 18432,  sm + 27136 };

    const int tid  = threadIdx.x;
    const int lane = tid & 31;
    const int wid  = tid >> 5;
    const int wm   = (wid & 1) * 64;
    const int wn   = (wid >> 1) * 32;
    const int bm   = blockIdx.y * BM;
    const int bn   = blockIdx.x * BN;

    float acc[4][4][4];
    #pragma unroll
    for (int i = 0; i < 4; i++)
        #pragma unroll
        for (int j = 0; j < 4; j++)
            #pragma unroll
            for (int r = 0; r < 4; r++) acc[i][j][r] = 0.f;

    const int NK = K / BK;

    #define G_LOAD(ST, KS) do {                                               \
        const int k0 = (KS) * BK;                                             \
        _Pragma("unroll")                                                     \
        for (int s = 0; s < 4; s++) {                                         \
            int t = tid + s * 256;                                            \
            int row = t >> 3, ch = (t & 7) * 8;                               \
            cpa16(AH[ST] + row * SA2 + ch,                                    \
                  A + (size_t)(bm + row) * K + k0 + ch);                      \
        }                                                                     \
        _Pragma("unroll")                                                     \
        for (int s = 0; s < 4; s++) {                                         \
            int t = tid + s * 256;                                            \
            int row = t >> 4, ch = (t & 15) * 8;                              \
            cpa16(BS[ST] + row * SB2 + ch,                                    \
                  B + (size_t)(k0 + row) * N + bn + ch);                      \
        }                                                                     \
        cp_commit();                                                          \
    } while (0)

    G_LOAD(0, 0);

    const int arow = lane & 15;
    const int acol = (lane >> 4) * 8;

    for (int ks = 0; ks < NK; ks++) {
        const int st = ks & 1;
        cp_wait0();
        __syncthreads();
        if (ks + 1 < NK) G_LOAD(st ^ 1, ks + 1);

        #pragma unroll
        for (int kk = 0; kk < 4; kk++) {
            uint32_t af[4][4];
            uint32_t bf[4][2];
            #pragma unroll
            for (int mf = 0; mf < 4; mf++)
                ldsm4(af[mf][0], af[mf][1], af[mf][2], af[mf][3],
                      &AH[st][(wm + mf * 16 + arow) * SA2 + kk * 16 + acol]);
            #pragma unroll
            for (int nf2 = 0; nf2 < 2; nf2++) {
                uint32_t r0, r1, r2, r3;
                ldsm4t(r0, r1, r2, r3,
                       &BS[st][(kk * 16 + arow) * SB2 + wn + nf2 * 16 + acol]);
                bf[nf2 * 2 + 0][0] = r0; bf[nf2 * 2 + 0][1] = r1;
                bf[nf2 * 2 + 1][0] = r2; bf[nf2 * 2 + 1][1] = r3;
            }
            #pragma unroll
            for (int mf = 0; mf < 4; mf++)
                #pragma unroll
                for (int nf = 0; nf < 4; nf++)
                    mma16816(acc[mf][nf], af[mf], bf[nf]);
        }
    }
    #undef G_LOAD

    const int r  = lane >> 2;
    const int c2 = (lane & 3) * 2;
    #pragma unroll
    for (int nf = 0; nf < 4; nf++) {
        const int col = bn + wn + nf * 8 + c2;
        const float b0 = bias[col];
        const float b1 = bias[col + 1];
        #pragma unroll
        for (int mf = 0; mf < 4; mf++) {
            const int row0 = bm + wm + mf * 16 + r;
            float v00 = acc[mf][nf][0] + b0, v01 = acc[mf][nf][1] + b1;
            float v10 = acc[mf][nf][2] + b0, v11 = acc[mf][nf][3] + b1;
            if (Cf) {
                *(float2*)(Cf + (size_t)row0 * N + col) = make_float2(v00, v01);
                *(float2*)(Cf + (size_t)(row0 + 8) * N + col) = make_float2(v10, v11);
            } else {
                *(uint32_t*)(Ch + (size_t)row0 * N + col) =
                    h2pack(__float2half_rn(v00), __float2half_rn(v01));
                *(uint32_t*)(Ch + (size_t)(row0 + 8) * N + col) =
                    h2pack(__float2half_rn(v10), __float2half_rn(v11));
            }
        }
    }
}

// ---------------------------------------------------------------------------
// Persistent tensor-core flash attention (round-15 configuration, verified
// best): 4 CTAs/SM, grid=592 (all 148 SMs covered), no register cap beyond
// the natural 128. S in log2 domain, P via packed ex2.approx.f16x2, row sums
// via ones-mma, one barrier per k-iteration.
// ---------------------------------------------------------------------------
#define AST 72
#define ATILE (64 * AST)
#define NTILES (BATCH * NH * (SEQ / 64))   // 1024
#define ATTN_GRID 592                      // 148 SMs x 4 CTAs

__global__ __launch_bounds__(128, 4) void attn_f16(
    const __half* __restrict__ qkv,
    __half* __restrict__ ctx)
{
    extern __shared__ __half smA[];

    const int tid  = threadIdx.x;
    const int lane = tid & 31;
    const int wid  = tid >> 5;

    const int krow = lane & 15;
    const int kcb  = (lane >> 4) * 8;

    const __half2 qscale = __halves2half2(__float2half_rn(0.18033688f),
                                          __float2half_rn(0.18033688f));
    const uint32_t ones_b[2] = { 0x3C003C00u, 0x3C003C00u };

    for (int tile = blockIdx.x; tile < NTILES; tile += ATTN_GRID) {
        const int qt = tile & 31;
        const int h  = (tile >> 5) & 15;
        const int b  = tile >> 9;

        const __half* qb = qkv + (size_t)b * SEQ * NQKV + h * HD;

        #pragma unroll
        for (int i = 0; i < 4; i++) {
            int c = tid + i * 128;
            int r = c >> 3, cc = (c & 7) * 8;
            cpa16(&smA[r * AST + cc], qb + (size_t)(qt * 64 + r) * NQKV + cc);
        }
        cp_commit(); cp_wait0(); __syncthreads();

        uint32_t qf[4][4];
        {
            const int row = wid * 16 + (lane & 15);
            const int cb  = (lane >> 4) * 8;
            #pragma unroll
            for (int j = 0; j < 4; j++) {
                ldsm4(qf[j][0], qf[j][1], qf[j][2], qf[j][3],
                      &smA[row * AST + j * 16 + cb]);
                #pragma unroll
                for (int r = 0; r < 4; r++) {
                    __half2 v = *reinterpret_cast<__half2*>(&qf[j][r]);
                    v = __hmul2(v, qscale);
                    qf[j][r] = *reinterpret_cast<uint32_t*>(&v);
                }
            }
        }
        __syncthreads();

        float oacc[8][4];
        #pragma unroll
        for (int nf = 0; nf < 8; nf++)
            #pragma unroll
            for (int r = 0; r < 4; r++) oacc[nf][r] = 0.f;
        float osum[4] = {0.f, 0.f, 0.f, 0.f};

        #define PREFETCH(KT, ST) do {                                          \
            __half* bp = smA + (ST) * 2 * ATILE;                               \
            _Pragma("unroll")                                                  \
            for (int i = 0; i < 4; i++) {                                      \
                int c = tid + i * 128;                                         \
                int r = c >> 3, cc = (c & 7) * 8;                              \
                size_t go = (size_t)((KT) * 64 + r) * NQKV + cc;               \
                cpa16(bp + r * AST + cc,          qb + D_MODEL + go);          \
                cpa16(bp + ATILE + r * AST + cc,  qb + 2 * D_MODEL + go);      \
            }                                                                  \
            cp_commit();                                                       \
        } while (0)

        PREFETCH(0, 0);

        for (int kt = 0; kt < SEQ / 64; kt++) {
            const int st = kt & 1;
            cp_wait0();
            __syncthreads();
            if (kt + 1 < SEQ / 64) PREFETCH(kt + 1, st ^ 1);

            const __half* KT_ = smA + st * 2 * ATILE;
            const __half* VT_ = KT_ + ATILE;

            float sacc[8][4];
            #pragma unroll
            for (int nf = 0; nf < 8; nf++)
                #pragma unroll
                for (int r = 0; r < 4; r++) sacc[nf][r] = 0.f;

            #pragma unroll
            for (int j = 0; j < 4; j++) {
                uint32_t bh[8][2];
                #pragma unroll
                for (int n2 = 0; n2 < 4; n2++) {
                    uint32_t t0, t1, t2, t3;
                    ldsm4(t0, t1, t2, t3,
                          &KT_[(n2 * 16 + krow) * AST + j * 16 + kcb]);
                    bh[n2*2][0] = t0; bh[n2*2][1] = t2;
                    bh[n2*2+1][0] = t1; bh[n2*2+1][1] = t3;
                }
                #pragma unroll
                for (int nf = 0; nf < 8; nf++)
                    mma16816(sacc[nf], qf[j], bh[nf]);
            }

            uint32_t ph[4][4];
            #pragma unroll
            for (int j = 0; j < 4; j++) {
                #pragma unroll
                for (int half = 0; half < 2; half++) {
                    ph[j][half * 2 + 0] =
                        ex2h2(packf2(sacc[2*j + half][0], sacc[2*j + half][1]));
                    ph[j][half * 2 + 1] =
                        ex2h2(packf2(sacc[2*j + half][2], sacc[2*j + half][3]));
                }
            }

            #pragma unroll
            for (int j = 0; j < 4; j++)
                mma16816(osum, ph[j], ones_b);

            #pragma unroll
            for (int j = 0; j < 4; j++) {
                uint32_t vh[8][2];
                #pragma unroll
                for (int n2 = 0; n2 < 4; n2++) {
                    uint32_t t0, t1, t2, t3;
                    ldsm4t(t0, t1, t2, t3,
                           &VT_[(j * 16 + krow) * AST + n2 * 16 + kcb]);
                    vh[n2*2][0] = t0; vh[n2*2][1] = t1;
                    vh[n2*2+1][0] = t2; vh[n2*2+1][1] = t3;
                }
                #pragma unroll
                for (int nf = 0; nf < 8; nf++)
                    mma16816(oacc[nf], ph[j], vh[nf]);
            }
        }
        #undef PREFETCH

        const float inv0 = 1.f / osum[0];
        const float inv1 = 1.f / osum[2];
        const int r0 = lane >> 2;
        const int colb = h * HD + (lane & 3) * 2;
        const size_t row0 = (size_t)b * SEQ + qt * 64 + wid * 16 + r0;
        #pragma unroll
        for (int nf = 0; nf < 8; nf++) {
            const int col = colb + nf * 8;
            *(uint32_t*)(ctx + row0 * D_MODEL + col) =
                h2pack(__float2half_rn(oacc[nf][0] * inv0),
                       __float2half_rn(oacc[nf][1] * inv0));
            *(uint32_t*)(ctx + (row0 + 8) * D_MODEL + col) =
                h2pack(__float2half_rn(oacc[nf][2] * inv1),
                       __float2half_rn(oacc[nf][3] * inv1));
        }
        __syncthreads();
    }
}

// ---------------------------------------------------------------------------
extern "C" void kernel_launch(void* const* d_in, const int* in_sizes, int n_in,
                              void* d_out, int out_size)
{
    const float* x    = (const float*)d_in[0];
    const float* Wqkv = (const float*)d_in[1];
    const float* bqkv = (const float*)d_in[2];
    const float* Wout = (const float*)d_in[3];
    const float* bout = (const float*)d_in[4];
    float* out = (float*)d_out;

    __half *xc, *wq, *qv, *cx, *wo;
    cudaGetSymbolAddress((void**)&xc, g_x);
    cudaGetSymbolAddress((void**)&wq, g_wqkv);
    cudaGetSymbolAddress((void**)&qv, g_qkv);
    cudaGetSymbolAddress((void**)&cx, g_ctx);
    cudaGetSymbolAddress((void**)&wo, g_wout);

    cast_all<<<2048, 256>>>((const float2*)x, (const float2*)Wqkv,
                            (const float2*)Wout,
                            (__half2*)xc, (__half2*)wq, (__half2*)wo);

    cudaFuncSetAttribute(gemm_f16, cudaFuncAttributeMaxDynamicSharedMemorySize,
                         GEMM_SMEM_BYTES);

    // 1) QKV projection -> fp16 qkv
    dim3 g1(NQKV / BN, MTOT / BM);
    gemm_f16<<<g1, 256, GEMM_SMEM_BYTES>>>(
        xc, wq, bqkv, nullptr, qv, MTOT, NQKV, D_MODEL);

    // 2) Persistent attention -> fp16 ctx (4 CTAs/SM, grid covers all SMs)
    size_t smem = (size_t)2 * 2 * ATILE * sizeof(__half);  // 36864 B
    cudaFuncSetAttribute(attn_f16, cudaFuncAttributeMaxDynamicSharedMemorySize,
                         (int)smem);
    attn_f16<<<ATTN_GRID, 128, smem>>>(qv, cx);

    // 3) Output projection -> fp32 out
    dim3 g3(D_MODEL / BN, MTOT / BM);
    gemm_f16<<<g3, 256, GEMM_SMEM_BYTES>>>(
        cx, wo, bout, out, nullptr, MTOT, D_MODEL, D_MODEL);
}